// round 1
// baseline (speedup 1.0000x reference)
#include <cuda_runtime.h>
#include <math.h>

#define N_NODES 50000
#define N_EDGES 600000
#define HID 128

// Scratch (allowed: __device__ globals, no runtime allocation)
__device__ float g_h[(size_t)N_NODES * HID];    // x @ fc1_w.T
__device__ float g_agg[(size_t)N_NODES * HID];  // scatter-add accumulator

// shifted softplus: softplus(x) - ln(2), numerically stable
__device__ __forceinline__ float sspf(float x) {
    return fmaxf(x, 0.0f) + log1pf(__expf(-fabsf(x))) - 0.69314718055994530942f;
}

// SMEM tile: k-major [k][m] with XOR swizzle on 16-float groups so that
//  - loader STS (fixed k per store, consecutive m)          -> conflict-free
//  - compute a-frag loads (fixed k, fixed m per half-warp)  -> broadcast
//  - compute b-frag loads (fixed k, m = tc*8 across lanes)  -> conflict-free
//  - transposed ssp epilogue stores (k = n = tc*8+j varies) -> spread via (k>>3)
#define AS_OFF(k, m) (((k) << 7) + (((((m) >> 4) ^ (((k) >> 3) & 7)) << 4) | ((m) & 15)))
#define TILE_FLOATS (128 * 128)

// Load a [128 rows x 128 cols] row-major global tile into k-major swizzled SMEM.
// Rows >= nrows are zero-filled.
__device__ __forceinline__ void load_tileT(const float* __restrict__ G, int row0,
                                           int nrows, float* S) {
    #pragma unroll
    for (int it = 0; it < 16; ++it) {
        int idx = threadIdx.x + it * 256;   // 0..4095
        int kq  = idx >> 7;                  // float4 index along k: 0..31
        int m   = idx & 127;                 // row within tile
        int row = row0 + m;
        float4 v = make_float4(0.f, 0.f, 0.f, 0.f);
        if (row < nrows) v = *(const float4*)&G[(size_t)row * 128 + kq * 4];
        int k = kq * 4;
        S[AS_OFF(k + 0, m)] = v.x;
        S[AS_OFF(k + 1, m)] = v.y;
        S[AS_OFF(k + 2, m)] = v.z;
        S[AS_OFF(k + 3, m)] = v.w;
    }
}

// acc[i][j] += sum_k As[k][tr*8+i] * Bs[k][tc*8+j]
__device__ __forceinline__ void gemm_tile(const float* __restrict__ As,
                                          const float* __restrict__ Bs,
                                          float acc[8][8]) {
    const int tr = threadIdx.x >> 4;
    const int tc = threadIdx.x & 15;
    const int ma = tr * 8;
    const int mb = tc * 8;
    #pragma unroll 4
    for (int k = 0; k < 128; ++k) {
        const float* ap = &As[AS_OFF(k, ma)];
        const float* bp = &Bs[AS_OFF(k, mb)];
        float4 a0 = *(const float4*)ap;
        float4 a1 = *(const float4*)(ap + 4);
        float4 b0 = *(const float4*)bp;
        float4 b1 = *(const float4*)(bp + 4);
        float a[8] = {a0.x, a0.y, a0.z, a0.w, a1.x, a1.y, a1.z, a1.w};
        float b[8] = {b0.x, b0.y, b0.z, b0.w, b1.x, b1.y, b1.z, b1.w};
        #pragma unroll
        for (int i = 0; i < 8; ++i)
            #pragma unroll
            for (int j = 0; j < 8; ++j)
                acc[i][j] = fmaf(a[i], b[j], acc[i][j]);
    }
}

__device__ __forceinline__ void zero_acc(float acc[8][8]) {
    #pragma unroll
    for (int i = 0; i < 8; ++i)
        #pragma unroll
        for (int j = 0; j < 8; ++j) acc[i][j] = 0.0f;
}

__device__ __forceinline__ void red_add_v4(float* addr, float4 v) {
    asm volatile("red.global.add.v4.f32 [%0], {%1, %2, %3, %4};"
                 :: "l"(addr), "f"(v.x), "f"(v.y), "f"(v.z), "f"(v.w)
                 : "memory");
}

// --------------------------------------------------------------------------
// Kernel 1: h = x @ fc1_w.T ; also zero g_agg
// --------------------------------------------------------------------------
__global__ void __launch_bounds__(256) node_h_kernel(const float* __restrict__ x,
                                                     const float* __restrict__ fc1_w) {
    extern __shared__ float sm[];
    float* As = sm;
    float* Bs = sm + TILE_FLOATS;
    const int row0 = blockIdx.x * 128;

    load_tileT(x, row0, N_NODES, As);
    load_tileT(fc1_w, 0, 128, Bs);
    __syncthreads();

    float acc[8][8];
    zero_acc(acc);
    gemm_tile(As, Bs, acc);

    const int tr = threadIdx.x >> 4;
    const int tc = threadIdx.x & 15;
    #pragma unroll
    for (int i = 0; i < 8; ++i) {
        int r = row0 + tr * 8 + i;
        if (r < N_NODES) {
            float* hp = &g_h[(size_t)r * 128 + tc * 8];
            *(float4*)hp       = make_float4(acc[i][0], acc[i][1], acc[i][2], acc[i][3]);
            *(float4*)(hp + 4) = make_float4(acc[i][4], acc[i][5], acc[i][6], acc[i][7]);
        }
    }

    // zero the agg tile for this block's rows
    const float4 z4 = make_float4(0.f, 0.f, 0.f, 0.f);
    #pragma unroll
    for (int it = 0; it < 16; ++it) {
        int idx = threadIdx.x + it * 256;   // 0..4095 float4 slots
        int m = idx >> 5;
        int q = idx & 31;
        int r = row0 + m;
        if (r < N_NODES) *(float4*)&g_agg[(size_t)r * 128 + q * 4] = z4;
    }
}

// --------------------------------------------------------------------------
// Kernel 2 (fused): W = ssp(ssp(ea @ f_w1.T + b1) @ f_w2.T + b2);
//                   msg = h[src] * W; atomic scatter-add into g_agg[dst]
// --------------------------------------------------------------------------
__global__ void __launch_bounds__(256) edge_kernel(const float* __restrict__ ea,
                                                   const int* __restrict__ ei,
                                                   const float* __restrict__ fw1,
                                                   const float* __restrict__ fb1,
                                                   const float* __restrict__ fw2,
                                                   const float* __restrict__ fb2) {
    extern __shared__ float sm[];
    float* As = sm;
    float* Bs = sm + TILE_FLOATS;
    int* src_s = (int*)(sm + 2 * TILE_FLOATS);
    int* dst_s = src_s + 128;

    const int row0 = blockIdx.x * 128;

    if (threadIdx.x < 128) {
        int e = row0 + threadIdx.x;
        src_s[threadIdx.x] = (e < N_EDGES) ? ei[e] : 0;
        dst_s[threadIdx.x] = (e < N_EDGES) ? ei[N_EDGES + e] : 0;
    }
    load_tileT(ea, row0, N_EDGES, As);
    load_tileT(fw1, 0, 128, Bs);
    __syncthreads();

    float acc[8][8];
    zero_acc(acc);
    gemm_tile(As, Bs, acc);   // Y1 = ea @ f_w1.T
    __syncthreads();          // all reads of As/Bs done

    const int tr = threadIdx.x >> 4;
    const int tc = threadIdx.x & 15;

    // ssp(Y1 + b1) -> As (transposed, k-major for stage 2)
    #pragma unroll
    for (int j = 0; j < 8; ++j) {
        int n = tc * 8 + j;
        float b = fb1[n];
        float4 v0 = make_float4(sspf(acc[0][j] + b), sspf(acc[1][j] + b),
                                sspf(acc[2][j] + b), sspf(acc[3][j] + b));
        float4 v1 = make_float4(sspf(acc[4][j] + b), sspf(acc[5][j] + b),
                                sspf(acc[6][j] + b), sspf(acc[7][j] + b));
        float* p = &As[AS_OFF(n, tr * 8)];
        *(float4*)p       = v0;
        *(float4*)(p + 4) = v1;
    }
    load_tileT(fw2, 0, 128, Bs);
    __syncthreads();

    zero_acc(acc);
    gemm_tile(As, Bs, acc);   // Y2 = ssp(Y1+b1) @ f_w2.T

    // W = ssp(Y2 + b2); msg = h[src] * W; scatter-add to g_agg[dst]
    float b2[8];
    #pragma unroll
    for (int j = 0; j < 8; ++j) b2[j] = fb2[tc * 8 + j];

    #pragma unroll
    for (int i = 0; i < 8; ++i) {
        int m = tr * 8 + i;
        int e = row0 + m;
        if (e < N_EDGES) {
            int s = src_s[m];
            int d = dst_s[m];
            const float* hp = &g_h[(size_t)s * 128 + tc * 8];
            float4 h0 = *(const float4*)hp;
            float4 h1 = *(const float4*)(hp + 4);
            float4 m0, m1;
            m0.x = h0.x * sspf(acc[i][0] + b2[0]);
            m0.y = h0.y * sspf(acc[i][1] + b2[1]);
            m0.z = h0.z * sspf(acc[i][2] + b2[2]);
            m0.w = h0.w * sspf(acc[i][3] + b2[3]);
            m1.x = h1.x * sspf(acc[i][4] + b2[4]);
            m1.y = h1.y * sspf(acc[i][5] + b2[5]);
            m1.z = h1.z * sspf(acc[i][6] + b2[6]);
            m1.w = h1.w * sspf(acc[i][7] + b2[7]);
            float* ap = &g_agg[(size_t)d * 128 + tc * 8];
            red_add_v4(ap, m0);
            red_add_v4(ap + 4, m1);
        }
    }
}

// --------------------------------------------------------------------------
// Kernel 3 (fused): out = ssp(agg @ s_w1.T) @ s_w2.T
// --------------------------------------------------------------------------
__global__ void __launch_bounds__(256) final_kernel(const float* __restrict__ sw1,
                                                    const float* __restrict__ sw2,
                                                    float* __restrict__ out) {
    extern __shared__ float sm[];
    float* As = sm;
    float* Bs = sm + TILE_FLOATS;
    const int row0 = blockIdx.x * 128;

    load_tileT(g_agg, row0, N_NODES, As);
    load_tileT(sw1, 0, 128, Bs);
    __syncthreads();

    float acc[8][8];
    zero_acc(acc);
    gemm_tile(As, Bs, acc);
    __syncthreads();

    const int tr = threadIdx.x >> 4;
    const int tc = threadIdx.x & 15;

    #pragma unroll
    for (int j = 0; j < 8; ++j) {
        int n = tc * 8 + j;
        float4 v0 = make_float4(sspf(acc[0][j]), sspf(acc[1][j]),
                                sspf(acc[2][j]), sspf(acc[3][j]));
        float4 v1 = make_float4(sspf(acc[4][j]), sspf(acc[5][j]),
                                sspf(acc[6][j]), sspf(acc[7][j]));
        float* p = &As[AS_OFF(n, tr * 8)];
        *(float4*)p       = v0;
        *(float4*)(p + 4) = v1;
    }
    load_tileT(sw2, 0, 128, Bs);
    __syncthreads();

    zero_acc(acc);
    gemm_tile(As, Bs, acc);

    #pragma unroll
    for (int i = 0; i < 8; ++i) {
        int r = row0 + tr * 8 + i;
        if (r < N_NODES) {
            float* op = &out[(size_t)r * 128 + tc * 8];
            *(float4*)op       = make_float4(acc[i][0], acc[i][1], acc[i][2], acc[i][3]);
            *(float4*)(op + 4) = make_float4(acc[i][4], acc[i][5], acc[i][6], acc[i][7]);
        }
    }
}

// --------------------------------------------------------------------------
extern "C" void kernel_launch(void* const* d_in, const int* in_sizes, int n_in,
                              void* d_out, int out_size) {
    const float* x    = (const float*)d_in[0];
    const float* ea   = (const float*)d_in[1];
    const int*   ei   = (const int*)d_in[2];
    const float* fc1w = (const float*)d_in[3];
    const float* fw1  = (const float*)d_in[4];
    const float* fb1  = (const float*)d_in[5];
    const float* fw2  = (const float*)d_in[6];
    const float* fb2  = (const float*)d_in[7];
    const float* sw1  = (const float*)d_in[8];
    const float* sw2  = (const float*)d_in[9];
    float* out = (float*)d_out;

    const size_t shmem = (size_t)(2 * TILE_FLOATS) * sizeof(float) + 256 * sizeof(int);

    cudaFuncSetAttribute(node_h_kernel, cudaFuncAttributeMaxDynamicSharedMemorySize, (int)shmem);
    cudaFuncSetAttribute(edge_kernel,   cudaFuncAttributeMaxDynamicSharedMemorySize, (int)shmem);
    cudaFuncSetAttribute(final_kernel,  cudaFuncAttributeMaxDynamicSharedMemorySize, (int)shmem);

    const int node_blocks = (N_NODES + 127) / 128;   // 391
    const int edge_blocks = (N_EDGES + 127) / 128;   // 4688

    node_h_kernel<<<node_blocks, 256, shmem>>>(x, fc1w);
    edge_kernel<<<edge_blocks, 256, shmem>>>(ea, ei, fw1, fb1, fw2, fb2);
    final_kernel<<<node_blocks, 256, shmem>>>(sw1, sw2, out);
}

// round 3
// speedup vs baseline: 2.2325x; 2.2325x over previous
#include <cuda_runtime.h>
#include <cstdint>
#include <math.h>

#define N_NODES 50000
#define N_EDGES 600000
#define HID 128

// Scratch
__device__ float g_h[(size_t)N_NODES * HID];    // x @ fc1_w.T (exact fp32)
__device__ float g_agg[(size_t)N_NODES * HID];  // scatter-add accumulator

// Fast shifted softplus: max(x,0) + log(1 + exp(-|x|)) - ln2
__device__ __forceinline__ float sspf(float x) {
    float t = __expf(-fabsf(x));
    return fmaxf(x, 0.0f) + __logf(1.0f + t) - 0.69314718055994530942f;
}

__device__ __forceinline__ float to_tf32(float x) {
    float r;
    asm("cvt.rna.tf32.f32 %0, %1;" : "=f"(r) : "f"(x));
    return r;
}

// m16n8k8 tf32 MMA (non-'a' PTX, valid on plain sm_103)
__device__ __forceinline__ void mma16n8k8(float c[4], const uint32_t a[4],
                                          const uint32_t b[2]) {
    asm volatile(
        "mma.sync.aligned.m16n8k8.row.col.f32.tf32.tf32.f32 "
        "{%0,%1,%2,%3}, {%4,%5,%6,%7}, {%8,%9}, {%0,%1,%2,%3};"
        : "+f"(c[0]), "+f"(c[1]), "+f"(c[2]), "+f"(c[3])
        : "r"(a[0]), "r"(a[1]), "r"(a[2]), "r"(a[3]), "r"(b[0]), "r"(b[1]));
}

__device__ __forceinline__ void red_add_v4(float* addr, float4 v) {
    asm volatile("red.global.add.v4.f32 [%0], {%1, %2, %3, %4};"
                 :: "l"(addr), "f"(v.x), "f"(v.y), "f"(v.z), "f"(v.w) : "memory");
}

// ==========================================================================
// Edge kernel: tf32 mma.sync filter MLP + fused gather/scatter
// ==========================================================================
#define ETHREADS 256
#define TILES_PER_CTA 8
#define EGRID 586            // 586*8 = 4688 tiles >= 600000/128
#define S 132                // padded fp32 row stride (conflict-free fragments)

// dyn smem layout (floats unless noted)
// [0..128)   src (int)   [128..256) dst (int)
// [256..384) b1          [384..512) b2
// [512 ..)   As  128*S
// then W1s 128*S, W2s 128*S
#define SM_IDX 0
#define SM_B1 256
#define SM_B2 384
#define SM_AS 512
#define SM_W1 (512 + 128 * S)
#define SM_W2 (512 + 2 * 128 * S)
#define SM_EDGE_FLOATS (512 + 3 * 128 * S)

// Load [128 x 128] row-major fp32 tile into padded smem, rounding to tf32.
__device__ __forceinline__ void load_tile_tf32(const float* __restrict__ G, int row0,
                                               int nrows, float* Sm) {
    #pragma unroll
    for (int i = 0; i < 16; ++i) {
        int idx = threadIdx.x + i * ETHREADS;  // 0..4095 float4 slots
        int row = idx >> 5;
        int q = idx & 31;
        float4 v = make_float4(0.f, 0.f, 0.f, 0.f);
        if (row0 + row < nrows) v = *(const float4*)&G[(size_t)(row0 + row) * 128 + q * 4];
        v.x = to_tf32(v.x); v.y = to_tf32(v.y); v.z = to_tf32(v.z); v.w = to_tf32(v.w);
        *(float4*)&Sm[row * S + q * 4] = v;
    }
}

// One 128x128x128 GEMM: acc += As(128xK) * Ws(NxK)^T, warp covers 32x64 block.
__device__ __forceinline__ void warp_gemm(const float* __restrict__ As,
                                          const float* __restrict__ Ws,
                                          float acc[2][8][4], int mb, int nb) {
    const int lid = threadIdx.x & 31;
    const int gr = lid >> 2;   // group id 0..7
    const int gc = lid & 3;    // thread-in-group 0..3
    const float* abase = As + (mb * 32 + gr) * S + gc;
    const float* bbase = Ws + (nb * 64 + gr) * S + gc;

    #pragma unroll 4
    for (int ks = 0; ks < 16; ++ks) {
        const int k0 = ks * 8;
        uint32_t a[2][4];
        #pragma unroll
        for (int mi = 0; mi < 2; ++mi) {
            const float* ap = abase + mi * 16 * S + k0;
            a[mi][0] = __float_as_uint(ap[0]);
            a[mi][1] = __float_as_uint(ap[8 * S]);
            a[mi][2] = __float_as_uint(ap[4]);
            a[mi][3] = __float_as_uint(ap[8 * S + 4]);
        }
        #pragma unroll
        for (int nj = 0; nj < 8; ++nj) {
            uint32_t b[2];
            const float* bp = bbase + nj * 8 * S + k0;
            b[0] = __float_as_uint(bp[0]);
            b[1] = __float_as_uint(bp[4]);
            mma16n8k8(acc[0][nj], a[0], b);
            mma16n8k8(acc[1][nj], a[1], b);
        }
    }
}

__device__ __forceinline__ void zero_acc8(float acc[2][8][4]) {
    #pragma unroll
    for (int mi = 0; mi < 2; ++mi)
        #pragma unroll
        for (int nj = 0; nj < 8; ++nj)
            #pragma unroll
            for (int e = 0; e < 4; ++e) acc[mi][nj][e] = 0.0f;
}

// ssp(acc + bias) -> As (optionally rounding to tf32 for the next MMA)
__device__ __forceinline__ void ssp_writeback(float* __restrict__ Sm,
                                              const float* __restrict__ bias,
                                              float acc[2][8][4], int mb, int nb,
                                              bool round_tf32) {
    const int lid = threadIdx.x & 31;
    const int gr = lid >> 2;
    const int gc = lid & 3;
    #pragma unroll
    for (int mi = 0; mi < 2; ++mi) {
        int r0 = mb * 32 + mi * 16 + gr;
        #pragma unroll
        for (int nj = 0; nj < 8; ++nj) {
            int c0 = nb * 64 + nj * 8 + 2 * gc;
            float b0 = bias[c0], b1v = bias[c0 + 1];
            float2 lo, hi;
            lo.x = sspf(acc[mi][nj][0] + b0);
            lo.y = sspf(acc[mi][nj][1] + b1v);
            hi.x = sspf(acc[mi][nj][2] + b0);
            hi.y = sspf(acc[mi][nj][3] + b1v);
            if (round_tf32) {
                lo.x = to_tf32(lo.x); lo.y = to_tf32(lo.y);
                hi.x = to_tf32(hi.x); hi.y = to_tf32(hi.y);
            }
            *(float2*)&Sm[r0 * S + c0] = lo;
            *(float2*)&Sm[(r0 + 8) * S + c0] = hi;
        }
    }
}

__global__ void __launch_bounds__(ETHREADS, 1)
edge_kernel(const float* __restrict__ ea, const int* __restrict__ ei,
            const float* __restrict__ fw1, const float* __restrict__ fb1,
            const float* __restrict__ fw2, const float* __restrict__ fb2) {
    extern __shared__ float sm[];
    int* src_s = (int*)&sm[SM_IDX];
    int* dst_s = src_s + 128;
    float* b1s = &sm[SM_B1];
    float* b2s = &sm[SM_B2];
    float* As = &sm[SM_AS];
    float* W1s = &sm[SM_W1];
    float* W2s = &sm[SM_W2];

    const int tid = threadIdx.x;
    const int wid = tid >> 5;
    const int mb = wid & 3;   // m-block: rows mb*32..+31
    const int nb = wid >> 2;  // n-block: cols nb*64..+63

    // weights + biases once per CTA
    load_tile_tf32(fw1, 0, 128, W1s);
    load_tile_tf32(fw2, 0, 128, W2s);
    if (tid < 128) {
        b1s[tid] = fb1[tid];
        b2s[tid] = fb2[tid];
    }
    __syncthreads();

    for (int it = 0; it < TILES_PER_CTA; ++it) {
        const int row0 = (blockIdx.x * TILES_PER_CTA + it) * 128;
        if (row0 >= N_EDGES) break;

        // load ea tile (tf32-rounded) + edge indices
        load_tile_tf32(ea, row0, N_EDGES, As);
        if (tid < 128) {
            int e = row0 + tid;
            src_s[tid] = (e < N_EDGES) ? ei[e] : 0;
            dst_s[tid] = (e < N_EDGES) ? ei[N_EDGES + e] : 0;
        }
        __syncthreads();

        float acc[2][8][4];

        // GEMM1: Y1 = ea @ W1^T
        zero_acc8(acc);
        warp_gemm(As, W1s, acc, mb, nb);
        __syncthreads();  // all reads of As complete

        // Z = tf32(ssp(Y1 + b1)) -> As
        ssp_writeback(As, b1s, acc, mb, nb, true);
        __syncthreads();

        // GEMM2: Y2 = Z @ W2^T
        zero_acc8(acc);
        warp_gemm(As, W2s, acc, mb, nb);
        __syncthreads();

        // W = ssp(Y2 + b2) -> As (full precision)
        ssp_writeback(As, b2s, acc, mb, nb, false);
        __syncthreads();

        // epilogue: half-warp per edge row; msg = h[src]*W; red.add -> agg[dst]
        {
            const int hw = tid >> 4;       // 0..15
            const int l16 = tid & 15;      // col group: 8 floats
            #pragma unroll
            for (int j = 0; j < 8; ++j) {
                int m = hw * 8 + j;
                int e = row0 + m;
                if (e < N_EDGES) {
                    int s = src_s[m];
                    int d = dst_s[m];
                    const float* wp = &As[m * S + l16 * 8];
                    const float* hp = &g_h[(size_t)s * 128 + l16 * 8];
                    float* ap = &g_agg[(size_t)d * 128 + l16 * 8];
                    float4 w0 = *(const float4*)wp;
                    float4 w1 = *(const float4*)(wp + 4);
                    float4 h0 = *(const float4*)hp;
                    float4 h1 = *(const float4*)(hp + 4);
                    float4 m0 = make_float4(w0.x * h0.x, w0.y * h0.y, w0.z * h0.z, w0.w * h0.w);
                    float4 m1 = make_float4(w1.x * h1.x, w1.y * h1.y, w1.z * h1.z, w1.w * h1.w);
                    red_add_v4(ap, m0);
                    red_add_v4(ap + 4, m1);
                }
            }
        }
        __syncthreads();  // epilogue reads of As done before next tile load
    }
}

// ==========================================================================
// fp32 CUDA-core GEMM path (node h + final MLP) — unchanged from R1 (passed)
// ==========================================================================
#define AS_OFF(k, m) (((k) << 7) + (((((m) >> 4) ^ (((k) >> 3) & 7)) << 4) | ((m) & 15)))
#define TILE_FLOATS (128 * 128)

__device__ __forceinline__ void load_tileT(const float* __restrict__ G, int row0,
                                           int nrows, float* Sm) {
    #pragma unroll
    for (int it = 0; it < 16; ++it) {
        int idx = threadIdx.x + it * 256;
        int kq = idx >> 7;
        int m = idx & 127;
        int row = row0 + m;
        float4 v = make_float4(0.f, 0.f, 0.f, 0.f);
        if (row < nrows) v = *(const float4*)&G[(size_t)row * 128 + kq * 4];
        int k = kq * 4;
        Sm[AS_OFF(k + 0, m)] = v.x;
        Sm[AS_OFF(k + 1, m)] = v.y;
        Sm[AS_OFF(k + 2, m)] = v.z;
        Sm[AS_OFF(k + 3, m)] = v.w;
    }
}

__device__ __forceinline__ void gemm_tile(const float* __restrict__ As,
                                          const float* __restrict__ Bs,
                                          float acc[8][8]) {
    const int tr = threadIdx.x >> 4;
    const int tc = threadIdx.x & 15;
    const int ma = tr * 8;
    const int mbx = tc * 8;
    #pragma unroll 4
    for (int k = 0; k < 128; ++k) {
        const float* ap = &As[AS_OFF(k, ma)];
        const float* bp = &Bs[AS_OFF(k, mbx)];
        float4 a0 = *(const float4*)ap;
        float4 a1 = *(const float4*)(ap + 4);
        float4 b0 = *(const float4*)bp;
        float4 b1 = *(const float4*)(bp + 4);
        float a[8] = {a0.x, a0.y, a0.z, a0.w, a1.x, a1.y, a1.z, a1.w};
        float b[8] = {b0.x, b0.y, b0.z, b0.w, b1.x, b1.y, b1.z, b1.w};
        #pragma unroll
        for (int i = 0; i < 8; ++i)
            #pragma unroll
            for (int j = 0; j < 8; ++j) acc[i][j] = fmaf(a[i], b[j], acc[i][j]);
    }
}

__device__ __forceinline__ void zero_acc(float acc[8][8]) {
    #pragma unroll
    for (int i = 0; i < 8; ++i)
        #pragma unroll
        for (int j = 0; j < 8; ++j) acc[i][j] = 0.0f;
}

__global__ void __launch_bounds__(256) node_h_kernel(const float* __restrict__ x,
                                                     const float* __restrict__ fc1_w) {
    extern __shared__ float smf[];
    float* As = smf;
    float* Bs = smf + TILE_FLOATS;
    const int row0 = blockIdx.x * 128;

    load_tileT(x, row0, N_NODES, As);
    load_tileT(fc1_w, 0, 128, Bs);
    __syncthreads();

    float acc[8][8];
    zero_acc(acc);
    gemm_tile(As, Bs, acc);

    const int tr = threadIdx.x >> 4;
    const int tc = threadIdx.x & 15;
    #pragma unroll
    for (int i = 0; i < 8; ++i) {
        int rr = row0 + tr * 8 + i;
        if (rr < N_NODES) {
            float* hp = &g_h[(size_t)rr * 128 + tc * 8];
            *(float4*)hp = make_float4(acc[i][0], acc[i][1], acc[i][2], acc[i][3]);
            *(float4*)(hp + 4) = make_float4(acc[i][4], acc[i][5], acc[i][6], acc[i][7]);
        }
    }

    const float4 z4 = make_float4(0.f, 0.f, 0.f, 0.f);
    #pragma unroll
    for (int it = 0; it < 16; ++it) {
        int idx = threadIdx.x + it * 256;
        int m = idx >> 5;
        int q = idx & 31;
        int rr = row0 + m;
        if (rr < N_NODES) *(float4*)&g_agg[(size_t)rr * 128 + q * 4] = z4;
    }
}

__global__ void __launch_bounds__(256) final_kernel(const float* __restrict__ sw1,
                                                    const float* __restrict__ sw2,
                                                    float* __restrict__ out) {
    extern __shared__ float smf[];
    float* As = smf;
    float* Bs = smf + TILE_FLOATS;
    const int row0 = blockIdx.x * 128;

    load_tileT(g_agg, row0, N_NODES, As);
    load_tileT(sw1, 0, 128, Bs);
    __syncthreads();

    float acc[8][8];
    zero_acc(acc);
    gemm_tile(As, Bs, acc);
    __syncthreads();

    const int tr = threadIdx.x >> 4;
    const int tc = threadIdx.x & 15;

    #pragma unroll
    for (int j = 0; j < 8; ++j) {
        int n = tc * 8 + j;
        float4 v0 = make_float4(sspf(acc[0][j]), sspf(acc[1][j]),
                                sspf(acc[2][j]), sspf(acc[3][j]));
        float4 v1 = make_float4(sspf(acc[4][j]), sspf(acc[5][j]),
                                sspf(acc[6][j]), sspf(acc[7][j]));
        float* p = &As[AS_OFF(n, tr * 8)];
        *(float4*)p = v0;
        *(float4*)(p + 4) = v1;
    }
    load_tileT(sw2, 0, 128, Bs);
    __syncthreads();

    zero_acc(acc);
    gemm_tile(As, Bs, acc);

    #pragma unroll
    for (int i = 0; i < 8; ++i) {
        int rr = row0 + tr * 8 + i;
        if (rr < N_NODES) {
            float* op = &out[(size_t)rr * 128 + tc * 8];
            *(float4*)op = make_float4(acc[i][0], acc[i][1], acc[i][2], acc[i][3]);
            *(float4*)(op + 4) = make_float4(acc[i][4], acc[i][5], acc[i][6], acc[i][7]);
        }
    }
}

// ==========================================================================
extern "C" void kernel_launch(void* const* d_in, const int* in_sizes, int n_in,
                              void* d_out, int out_size) {
    const float* x = (const float*)d_in[0];
    const float* ea = (const float*)d_in[1];
    const int* ei = (const int*)d_in[2];
    const float* fc1w = (const float*)d_in[3];
    const float* fw1 = (const float*)d_in[4];
    const float* fb1 = (const float*)d_in[5];
    const float* fw2 = (const float*)d_in[6];
    const float* fb2 = (const float*)d_in[7];
    const float* sw1 = (const float*)d_in[8];
    const float* sw2 = (const float*)d_in[9];
    float* out = (float*)d_out;

    const size_t shmem_fp32 = (size_t)(2 * TILE_FLOATS) * sizeof(float);
    const size_t shmem_edge = (size_t)SM_EDGE_FLOATS * sizeof(float);

    cudaFuncSetAttribute(node_h_kernel, cudaFuncAttributeMaxDynamicSharedMemorySize, (int)shmem_fp32);
    cudaFuncSetAttribute(final_kernel, cudaFuncAttributeMaxDynamicSharedMemorySize, (int)shmem_fp32);
    cudaFuncSetAttribute(edge_kernel, cudaFuncAttributeMaxDynamicSharedMemorySize, (int)shmem_edge);

    const int node_blocks = (N_NODES + 127) / 128;  // 391

    node_h_kernel<<<node_blocks, 256, shmem_fp32>>>(x, fc1w);
    edge_kernel<<<EGRID, ETHREADS, shmem_edge>>>(ea, ei, fw1, fb1, fw2, fb2);
    final_kernel<<<node_blocks, 256, shmem_fp32>>>(sw1, sw2, out);
}

// round 4
// speedup vs baseline: 2.3749x; 1.0637x over previous
#include <cuda_runtime.h>
#include <cstdint>
#include <math.h>

#define N_NODES 50000
#define N_EDGES 600000
#define HID 128

// Scratch
__device__ float g_h[(size_t)N_NODES * HID];    // x @ fc1_w.T
__device__ float g_agg[(size_t)N_NODES * HID];  // scatter-add accumulator

// Fast shifted softplus
__device__ __forceinline__ float sspf(float x) {
    float t = __expf(-fabsf(x));
    return fmaxf(x, 0.0f) + __logf(1.0f + t) - 0.69314718055994530942f;
}

__device__ __forceinline__ float to_tf32(float x) {
    float r;
    asm("cvt.rna.tf32.f32 %0, %1;" : "=f"(r) : "f"(x));
    return r;
}

__device__ __forceinline__ void mma16n8k8(float c[4], const uint32_t a[4],
                                          const uint32_t b[2]) {
    asm volatile(
        "mma.sync.aligned.m16n8k8.row.col.f32.tf32.tf32.f32 "
        "{%0,%1,%2,%3}, {%4,%5,%6,%7}, {%8,%9}, {%0,%1,%2,%3};"
        : "+f"(c[0]), "+f"(c[1]), "+f"(c[2]), "+f"(c[3])
        : "r"(a[0]), "r"(a[1]), "r"(a[2]), "r"(a[3]), "r"(b[0]), "r"(b[1]));
}

__device__ __forceinline__ void red_add_v4(float* addr, float4 v) {
    asm volatile("red.global.add.v4.f32 [%0], {%1, %2, %3, %4};"
                 :: "l"(addr), "f"(v.x), "f"(v.y), "f"(v.z), "f"(v.w) : "memory");
}

#define NT 256       // threads per CTA everywhere
#define SA 132       // padded fp32 stride of the A tile (conflict-free scalar frags)

// ==========================================================================
// Packed weight layout: Wp[n*128 + wcol(k,n)] = tf32(W[n][k])
// k-interleave: 16-k chunk c; within it pk-offset = (k&3)*4 + ((k>>2)&3),
// so a float4 at (16c + gc*4) ^ ((n&1)<<4) holds {k0+gc, k0+gc+4, k0+gc+8,
// k0+gc+12} -> both k-steps of the pair in ONE conflict-free LDS.128.
// ==========================================================================
__device__ __forceinline__ int wcol(int k, int n) {
    int pk = (k & ~15) | ((k & 3) << 2) | ((k >> 2) & 3);
    return pk ^ ((n & 1) << 4);
}

__device__ __forceinline__ void load_weights_packed(const float* __restrict__ G,
                                                    float* __restrict__ Wp) {
    for (int idx = threadIdx.x; idx < 128 * 32; idx += NT) {
        int n = idx >> 5, t = idx & 31;
        float4 v = *(const float4*)&G[n * 128 + t * 4];
        float vv[4] = {to_tf32(v.x), to_tf32(v.y), to_tf32(v.z), to_tf32(v.w)};
        #pragma unroll
        for (int i = 0; i < 4; ++i) Wp[n * 128 + wcol(t * 4 + i, n)] = vv[i];
    }
}

// Load [128 x 128] row-major fp32 tile into padded natural smem, tf32-rounded.
__device__ __forceinline__ void load_tileA(const float* __restrict__ G, int row0,
                                           int nrows, float* __restrict__ Sm) {
    #pragma unroll
    for (int i = 0; i < 16; ++i) {
        int idx = threadIdx.x + i * NT;  // 0..4095 float4 slots
        int row = idx >> 5;
        int q = idx & 31;
        float4 v = make_float4(0.f, 0.f, 0.f, 0.f);
        if (row0 + row < nrows) v = *(const float4*)&G[(size_t)(row0 + row) * 128 + q * 4];
        v.x = to_tf32(v.x); v.y = to_tf32(v.y); v.z = to_tf32(v.z); v.w = to_tf32(v.w);
        *(float4*)&Sm[row * SA + q * 4] = v;
    }
}

// 128x128x128 GEMM, warp tile 32x64: acc += A * Wp^T
__device__ __forceinline__ void warp_gemm(const float* __restrict__ As,
                                          const float* __restrict__ Wp,
                                          float acc[2][8][4], int mb, int nb) {
    const int lid = threadIdx.x & 31;
    const int gr = lid >> 2;
    const int gc = lid & 3;
    const float* abase = As + (mb * 32 + gr) * SA + gc;
    const int nrow0 = nb * 64 + gr;
    const int nxor = (gr & 1) << 4;

    #pragma unroll
    for (int c = 0; c < 8; ++c) {
        const int k0 = c * 16;
        uint32_t a[2][2][4];  // [mi][kstep][frag]
        #pragma unroll
        for (int mi = 0; mi < 2; ++mi) {
            const float* ap0 = abase + mi * 16 * SA + k0;
            const float* ap1 = ap0 + 8 * SA;
            a[mi][0][0] = __float_as_uint(ap0[0]);
            a[mi][0][1] = __float_as_uint(ap1[0]);
            a[mi][0][2] = __float_as_uint(ap0[4]);
            a[mi][0][3] = __float_as_uint(ap1[4]);
            a[mi][1][0] = __float_as_uint(ap0[8]);
            a[mi][1][1] = __float_as_uint(ap1[8]);
            a[mi][1][2] = __float_as_uint(ap0[12]);
            a[mi][1][3] = __float_as_uint(ap1[12]);
        }
        #pragma unroll
        for (int nj = 0; nj < 8; ++nj) {
            const int n = nrow0 + 8 * nj;
            float4 bv = *(const float4*)&Wp[n * 128 + ((k0 + gc * 4) ^ nxor)];
            uint32_t b0[2] = {__float_as_uint(bv.x), __float_as_uint(bv.y)};
            uint32_t b1[2] = {__float_as_uint(bv.z), __float_as_uint(bv.w)};
            mma16n8k8(acc[0][nj], a[0][0], b0);
            mma16n8k8(acc[1][nj], a[1][0], b0);
            mma16n8k8(acc[0][nj], a[0][1], b1);
            mma16n8k8(acc[1][nj], a[1][1], b1);
        }
    }
}

__device__ __forceinline__ void zero_acc8(float acc[2][8][4]) {
    #pragma unroll
    for (int mi = 0; mi < 2; ++mi)
        #pragma unroll
        for (int nj = 0; nj < 8; ++nj)
            #pragma unroll
            for (int e = 0; e < 4; ++e) acc[mi][nj][e] = 0.0f;
}

// ssp(acc + bias) -> As (natural layout), optional tf32 rounding
__device__ __forceinline__ void ssp_writeback(float* __restrict__ Sm,
                                              const float* __restrict__ bias,
                                              float acc[2][8][4], int mb, int nb,
                                              bool round_tf32) {
    const int lid = threadIdx.x & 31;
    const int gr = lid >> 2;
    const int gc = lid & 3;
    #pragma unroll
    for (int mi = 0; mi < 2; ++mi) {
        int r0 = mb * 32 + mi * 16 + gr;
        #pragma unroll
        for (int nj = 0; nj < 8; ++nj) {
            int c0 = nb * 64 + nj * 8 + 2 * gc;
            float b0 = bias[c0], b1v = bias[c0 + 1];
            float2 lo, hi;
            lo.x = sspf(acc[mi][nj][0] + b0);
            lo.y = sspf(acc[mi][nj][1] + b1v);
            hi.x = sspf(acc[mi][nj][2] + b0);
            hi.y = sspf(acc[mi][nj][3] + b1v);
            if (round_tf32) {
                lo.x = to_tf32(lo.x); lo.y = to_tf32(lo.y);
                hi.x = to_tf32(hi.x); hi.y = to_tf32(hi.y);
            }
            *(float2*)&Sm[r0 * SA + c0] = lo;
            *(float2*)&Sm[(r0 + 8) * SA + c0] = hi;
        }
    }
}

// ==========================================================================
// Edge kernel
// ==========================================================================
#define TILES_PER_CTA 8
#define EGRID 586  // 586*8 = 4688 tiles >= ceil(600000/128)

// smem layout (floats): idx 256 | b1 128 | b2 128 | As 128*SA | W1p 16384 | W2p 16384
#define ESM_IDX 0
#define ESM_B1 256
#define ESM_B2 384
#define ESM_AS 512
#define ESM_W1 (512 + 128 * SA)
#define ESM_W2 (512 + 128 * SA + 16384)
#define ESM_FLOATS (512 + 128 * SA + 32768)

__global__ void __launch_bounds__(NT, 1)
edge_kernel(const float* __restrict__ ea, const int* __restrict__ ei,
            const float* __restrict__ fw1, const float* __restrict__ fb1,
            const float* __restrict__ fw2, const float* __restrict__ fb2) {
    extern __shared__ float sm[];
    int* src_s = (int*)&sm[ESM_IDX];
    int* dst_s = src_s + 128;
    float* b1s = &sm[ESM_B1];
    float* b2s = &sm[ESM_B2];
    float* As = &sm[ESM_AS];
    float* W1p = &sm[ESM_W1];
    float* W2p = &sm[ESM_W2];

    const int tid = threadIdx.x;
    const int wid = tid >> 5;
    const int mb = wid & 3;
    const int nb = wid >> 2;

    load_weights_packed(fw1, W1p);
    load_weights_packed(fw2, W2p);
    if (tid < 128) {
        b1s[tid] = fb1[tid];
        b2s[tid] = fb2[tid];
    }
    __syncthreads();

    for (int it = 0; it < TILES_PER_CTA; ++it) {
        const int row0 = (blockIdx.x * TILES_PER_CTA + it) * 128;
        if (row0 >= N_EDGES) break;

        load_tileA(ea, row0, N_EDGES, As);
        if (tid < 128) {
            int e = row0 + tid;
            src_s[tid] = (e < N_EDGES) ? ei[e] : 0;
            dst_s[tid] = (e < N_EDGES) ? ei[N_EDGES + e] : 0;
        }
        __syncthreads();

        float acc[2][8][4];

        zero_acc8(acc);
        warp_gemm(As, W1p, acc, mb, nb);       // Y1 = ea @ W1^T
        __syncthreads();

        ssp_writeback(As, b1s, acc, mb, nb, true);  // Z = tf32(ssp(Y1+b1))
        __syncthreads();

        zero_acc8(acc);
        warp_gemm(As, W2p, acc, mb, nb);       // Y2 = Z @ W2^T
        __syncthreads();

        ssp_writeback(As, b2s, acc, mb, nb, false); // W = ssp(Y2+b2)
        __syncthreads();

        // epilogue: msg = h[src]*W; red.add -> agg[dst]
        {
            const int hw = tid >> 4;
            const int l16 = tid & 15;
            #pragma unroll
            for (int j = 0; j < 8; ++j) {
                int m = hw * 8 + j;
                int e = row0 + m;
                if (e < N_EDGES) {
                    int s = src_s[m];
                    int d = dst_s[m];
                    const float* wp = &As[m * SA + l16 * 8];
                    const float* hp = &g_h[(size_t)s * 128 + l16 * 8];
                    float* ap = &g_agg[(size_t)d * 128 + l16 * 8];
                    float4 w0 = *(const float4*)wp;
                    float4 w1 = *(const float4*)(wp + 4);
                    float4 h0 = *(const float4*)hp;
                    float4 h1 = *(const float4*)(hp + 4);
                    red_add_v4(ap, make_float4(w0.x * h0.x, w0.y * h0.y,
                                               w0.z * h0.z, w0.w * h0.w));
                    red_add_v4(ap + 4, make_float4(w1.x * h1.x, w1.y * h1.y,
                                                   w1.z * h1.z, w1.w * h1.w));
                }
            }
        }
        __syncthreads();
    }
}

// ==========================================================================
// Node h kernel (tf32 mma): h = x @ fc1^T ; zero g_agg
// smem: As 128*SA | Wp 16384
// ==========================================================================
#define NSM_AS 0
#define NSM_W (128 * SA)
#define NSM_FLOATS (128 * SA + 16384)

__global__ void __launch_bounds__(NT, 1)
node_h_kernel(const float* __restrict__ x, const float* __restrict__ fc1_w) {
    extern __shared__ float sm[];
    float* As = &sm[NSM_AS];
    float* Wp = &sm[NSM_W];

    const int tid = threadIdx.x;
    const int wid = tid >> 5;
    const int mb = wid & 3;
    const int nb = wid >> 2;
    const int row0 = blockIdx.x * 128;

    load_weights_packed(fc1_w, Wp);
    load_tileA(x, row0, N_NODES, As);
    __syncthreads();

    float acc[2][8][4];
    zero_acc8(acc);
    warp_gemm(As, Wp, acc, mb, nb);

    const int lid = tid & 31;
    const int gr = lid >> 2;
    const int gc = lid & 3;
    #pragma unroll
    for (int mi = 0; mi < 2; ++mi) {
        int r0 = row0 + mb * 32 + mi * 16 + gr;
        #pragma unroll
        for (int nj = 0; nj < 8; ++nj) {
            int c0 = nb * 64 + nj * 8 + 2 * gc;
            if (r0 < N_NODES)
                *(float2*)&g_h[(size_t)r0 * 128 + c0] =
                    make_float2(acc[mi][nj][0], acc[mi][nj][1]);
            if (r0 + 8 < N_NODES)
                *(float2*)&g_h[(size_t)(r0 + 8) * 128 + c0] =
                    make_float2(acc[mi][nj][2], acc[mi][nj][3]);
        }
    }

    const float4 z4 = make_float4(0.f, 0.f, 0.f, 0.f);
    #pragma unroll
    for (int i = 0; i < 16; ++i) {
        int idx = tid + i * NT;
        int m = idx >> 5;
        int q = idx & 31;
        int r = row0 + m;
        if (r < N_NODES) *(float4*)&g_agg[(size_t)r * 128 + q * 4] = z4;
    }
}

// ==========================================================================
// Final kernel (tf32 mma): out = ssp(agg @ s_w1^T) @ s_w2^T
// smem: bias0 128 | As 128*SA | W1p 16384 | W2p 16384
// ==========================================================================
#define FSM_B0 0
#define FSM_AS 128
#define FSM_W1 (128 + 128 * SA)
#define FSM_W2 (128 + 128 * SA + 16384)
#define FSM_FLOATS (128 + 128 * SA + 32768)

__global__ void __launch_bounds__(NT, 1)
final_kernel(const float* __restrict__ sw1, const float* __restrict__ sw2,
             float* __restrict__ out) {
    extern __shared__ float sm[];
    float* b0s = &sm[FSM_B0];
    float* As = &sm[FSM_AS];
    float* W1p = &sm[FSM_W1];
    float* W2p = &sm[FSM_W2];

    const int tid = threadIdx.x;
    const int wid = tid >> 5;
    const int mb = wid & 3;
    const int nb = wid >> 2;
    const int row0 = blockIdx.x * 128;

    load_weights_packed(sw1, W1p);
    load_weights_packed(sw2, W2p);
    if (tid < 128) b0s[tid] = 0.0f;
    load_tileA(g_agg, row0, N_NODES, As);
    __syncthreads();

    float acc[2][8][4];
    zero_acc8(acc);
    warp_gemm(As, W1p, acc, mb, nb);
    __syncthreads();

    ssp_writeback(As, b0s, acc, mb, nb, true);  // tf32(ssp(Y1))
    __syncthreads();

    zero_acc8(acc);
    warp_gemm(As, W2p, acc, mb, nb);

    const int lid = tid & 31;
    const int gr = lid >> 2;
    const int gc = lid & 3;
    #pragma unroll
    for (int mi = 0; mi < 2; ++mi) {
        int r0 = row0 + mb * 32 + mi * 16 + gr;
        #pragma unroll
        for (int nj = 0; nj < 8; ++nj) {
            int c0 = nb * 64 + nj * 8 + 2 * gc;
            if (r0 < N_NODES)
                *(float2*)&out[(size_t)r0 * 128 + c0] =
                    make_float2(acc[mi][nj][0], acc[mi][nj][1]);
            if (r0 + 8 < N_NODES)
                *(float2*)&out[(size_t)(r0 + 8) * 128 + c0] =
                    make_float2(acc[mi][nj][2], acc[mi][nj][3]);
        }
    }
}

// ==========================================================================
extern "C" void kernel_launch(void* const* d_in, const int* in_sizes, int n_in,
                              void* d_out, int out_size) {
    const float* x = (const float*)d_in[0];
    const float* ea = (const float*)d_in[1];
    const int* ei = (const int*)d_in[2];
    const float* fc1w = (const float*)d_in[3];
    const float* fw1 = (const float*)d_in[4];
    const float* fb1 = (const float*)d_in[5];
    const float* fw2 = (const float*)d_in[6];
    const float* fb2 = (const float*)d_in[7];
    const float* sw1 = (const float*)d_in[8];
    const float* sw2 = (const float*)d_in[9];
    float* out = (float*)d_out;

    const size_t sh_edge = (size_t)ESM_FLOATS * sizeof(float);
    const size_t sh_node = (size_t)NSM_FLOATS * sizeof(float);
    const size_t sh_final = (size_t)FSM_FLOATS * sizeof(float);

    cudaFuncSetAttribute(edge_kernel, cudaFuncAttributeMaxDynamicSharedMemorySize, (int)sh_edge);
    cudaFuncSetAttribute(node_h_kernel, cudaFuncAttributeMaxDynamicSharedMemorySize, (int)sh_node);
    cudaFuncSetAttribute(final_kernel, cudaFuncAttributeMaxDynamicSharedMemorySize, (int)sh_final);

    const int node_blocks = (N_NODES + 127) / 128;  // 391

    node_h_kernel<<<node_blocks, NT, sh_node>>>(x, fc1w);
    edge_kernel<<<EGRID, NT, sh_edge>>>(ea, ei, fw1, fb1, fw2, fb2);
    final_kernel<<<node_blocks, NT, sh_final>>>(sw1, sw2, out);
}

// round 5
// speedup vs baseline: 2.8291x; 1.1913x over previous
#include <cuda_runtime.h>
#include <cstdint>
#include <math.h>

#define N_NODES 50000
#define N_EDGES 600000
#define HID 128

// Scratch
__device__ float g_h[(size_t)N_NODES * HID];    // x @ fc1_w.T
__device__ float g_agg[(size_t)N_NODES * HID];  // scatter-add accumulator

// Fast shifted softplus
__device__ __forceinline__ float sspf(float x) {
    float t = __expf(-fabsf(x));
    return fmaxf(x, 0.0f) + __logf(1.0f + t) - 0.69314718055994530942f;
}

__device__ __forceinline__ float to_tf32(float x) {
    float r;
    asm("cvt.rna.tf32.f32 %0, %1;" : "=f"(r) : "f"(x));
    return r;
}

__device__ __forceinline__ void mma16n8k8(float c[4], const uint32_t a[4],
                                          const uint32_t b[2]) {
    asm volatile(
        "mma.sync.aligned.m16n8k8.row.col.f32.tf32.tf32.f32 "
        "{%0,%1,%2,%3}, {%4,%5,%6,%7}, {%8,%9}, {%0,%1,%2,%3};"
        : "+f"(c[0]), "+f"(c[1]), "+f"(c[2]), "+f"(c[3])
        : "r"(a[0]), "r"(a[1]), "r"(a[2]), "r"(a[3]), "r"(b[0]), "r"(b[1]));
}

__device__ __forceinline__ void red_add_v4(float* addr, float4 v) {
    asm volatile("red.global.add.v4.f32 [%0], {%1, %2, %3, %4};"
                 :: "l"(addr), "f"(v.x), "f"(v.y), "f"(v.z), "f"(v.w) : "memory");
}

#define BAR_GRP(id) asm volatile("bar.sync %0, 64;" :: "r"(id) : "memory")

#define NT 256       // threads per CTA everywhere
#define SA 132       // padded fp32 stride of the A tile

// ==========================================================================
// Packed weight layout (R4, proven): Wp[n*128 + wcol(k,n)] = tf32(W[n][k])
// ==========================================================================
__device__ __forceinline__ int wcol(int k, int n) {
    int pk = (k & ~15) | ((k & 3) << 2) | ((k >> 2) & 3);
    return pk ^ ((n & 1) << 4);
}

__device__ __forceinline__ void load_weights_packed(const float* __restrict__ G,
                                                    float* __restrict__ Wp) {
    for (int idx = threadIdx.x; idx < 128 * 32; idx += NT) {
        int n = idx >> 5, t = idx & 31;
        float4 v = *(const float4*)&G[n * 128 + t * 4];
        float vv[4] = {to_tf32(v.x), to_tf32(v.y), to_tf32(v.z), to_tf32(v.w)};
        #pragma unroll
        for (int i = 0; i < 4; ++i) Wp[n * 128 + wcol(t * 4 + i, n)] = vv[i];
    }
}

// Group-local load: 32 rows [row0+mb*32 .. +31] of a row-major [*,128] tensor
// into As rows mb*32..+31 (tf32-rounded). 64 threads (tg = tid&63).
__device__ __forceinline__ void load_rows32(const float* __restrict__ G, int grow0,
                                            int nrows, float* __restrict__ Sm,
                                            int srow0, int tg) {
    #pragma unroll
    for (int i = 0; i < 16; ++i) {
        int idx = tg + i * 64;   // 0..1023 float4 slots
        int r = idx >> 5;
        int q = idx & 31;
        float4 v = make_float4(0.f, 0.f, 0.f, 0.f);
        if (grow0 + r < nrows) v = *(const float4*)&G[(size_t)(grow0 + r) * 128 + q * 4];
        v.x = to_tf32(v.x); v.y = to_tf32(v.y); v.z = to_tf32(v.z); v.w = to_tf32(v.w);
        *(float4*)&Sm[(srow0 + r) * SA + q * 4] = v;
    }
}

// 32x128 warp-tile GEMM (rows mb*32..+31, cols nb*64..+63): acc += A * Wp^T
__device__ __forceinline__ void warp_gemm(const float* __restrict__ As,
                                          const float* __restrict__ Wp,
                                          float acc[2][8][4], int mb, int nb) {
    const int lid = threadIdx.x & 31;
    const int gr = lid >> 2;
    const int gc = lid & 3;
    const float* abase = As + (mb * 32 + gr) * SA + gc;
    const int nrow0 = nb * 64 + gr;
    const int nxor = (gr & 1) << 4;

    #pragma unroll
    for (int c = 0; c < 8; ++c) {
        const int k0 = c * 16;
        uint32_t a[2][2][4];
        #pragma unroll
        for (int mi = 0; mi < 2; ++mi) {
            const float* ap0 = abase + mi * 16 * SA + k0;
            const float* ap1 = ap0 + 8 * SA;
            a[mi][0][0] = __float_as_uint(ap0[0]);
            a[mi][0][1] = __float_as_uint(ap1[0]);
            a[mi][0][2] = __float_as_uint(ap0[4]);
            a[mi][0][3] = __float_as_uint(ap1[4]);
            a[mi][1][0] = __float_as_uint(ap0[8]);
            a[mi][1][1] = __float_as_uint(ap1[8]);
            a[mi][1][2] = __float_as_uint(ap0[12]);
            a[mi][1][3] = __float_as_uint(ap1[12]);
        }
        #pragma unroll
        for (int nj = 0; nj < 8; ++nj) {
            const int n = nrow0 + 8 * nj;
            float4 bv = *(const float4*)&Wp[n * 128 + ((k0 + gc * 4) ^ nxor)];
            uint32_t b0[2] = {__float_as_uint(bv.x), __float_as_uint(bv.y)};
            uint32_t b1[2] = {__float_as_uint(bv.z), __float_as_uint(bv.w)};
            mma16n8k8(acc[0][nj], a[0][0], b0);
            mma16n8k8(acc[1][nj], a[1][0], b0);
            mma16n8k8(acc[0][nj], a[0][1], b1);
            mma16n8k8(acc[1][nj], a[1][1], b1);
        }
    }
}

__device__ __forceinline__ void zero_acc8(float acc[2][8][4]) {
    #pragma unroll
    for (int mi = 0; mi < 2; ++mi)
        #pragma unroll
        for (int nj = 0; nj < 8; ++nj)
            #pragma unroll
            for (int e = 0; e < 4; ++e) acc[mi][nj][e] = 0.0f;
}

__device__ __forceinline__ void ssp_writeback(float* __restrict__ Sm,
                                              const float* __restrict__ bias,
                                              float acc[2][8][4], int mb, int nb,
                                              bool round_tf32) {
    const int lid = threadIdx.x & 31;
    const int gr = lid >> 2;
    const int gc = lid & 3;
    #pragma unroll
    for (int mi = 0; mi < 2; ++mi) {
        int r0 = mb * 32 + mi * 16 + gr;
        #pragma unroll
        for (int nj = 0; nj < 8; ++nj) {
            int c0 = nb * 64 + nj * 8 + 2 * gc;
            float b0 = bias ? bias[c0] : 0.0f;
            float b1v = bias ? bias[c0 + 1] : 0.0f;
            float2 lo, hi;
            lo.x = sspf(acc[mi][nj][0] + b0);
            lo.y = sspf(acc[mi][nj][1] + b1v);
            hi.x = sspf(acc[mi][nj][2] + b0);
            hi.y = sspf(acc[mi][nj][3] + b1v);
            if (round_tf32) {
                lo.x = to_tf32(lo.x); lo.y = to_tf32(lo.y);
                hi.x = to_tf32(hi.x); hi.y = to_tf32(hi.y);
            }
            *(float2*)&Sm[r0 * SA + c0] = lo;
            *(float2*)&Sm[(r0 + 8) * SA + c0] = hi;
        }
    }
}

// ==========================================================================
// Edge kernel: group-pipelined (4 groups x 2 warps, named barriers)
// ==========================================================================
#define TILES_PER_CTA 8
#define EGRID 586

#define ESM_IDX 0
#define ESM_B1 256
#define ESM_B2 384
#define ESM_AS 512
#define ESM_W1 (512 + 128 * SA)
#define ESM_W2 (512 + 128 * SA + 16384)
#define ESM_FLOATS (512 + 128 * SA + 32768)

__global__ void __launch_bounds__(NT, 1)
edge_kernel(const float* __restrict__ ea, const int* __restrict__ ei,
            const float* __restrict__ fw1, const float* __restrict__ fb1,
            const float* __restrict__ fw2, const float* __restrict__ fb2) {
    extern __shared__ float sm[];
    int* src_s = (int*)&sm[ESM_IDX];
    int* dst_s = src_s + 128;
    float* b1s = &sm[ESM_B1];
    float* b2s = &sm[ESM_B2];
    float* As = &sm[ESM_AS];
    float* W1p = &sm[ESM_W1];
    float* W2p = &sm[ESM_W2];

    const int tid = threadIdx.x;
    const int mb = tid >> 6;          // group 0..3: rows mb*32..+31
    const int nb = (tid >> 5) & 1;    // warp-in-group: cols nb*64..+63
    const int tg = tid & 63;          // thread-in-group
    const int bar = mb + 1;

    load_weights_packed(fw1, W1p);
    load_weights_packed(fw2, W2p);
    if (tid < 128) {
        b1s[tid] = fb1[tid];
        b2s[tid] = fb2[tid];
    }
    __syncthreads();

    for (int it = 0; it < TILES_PER_CTA; ++it) {
        const int row0 = (blockIdx.x * TILES_PER_CTA + it) * 128;
        if (row0 >= N_EDGES) break;

        // group-local loads: 32 A rows + 32 index pairs
        load_rows32(ea, row0 + mb * 32, N_EDGES, As, mb * 32, tg);
        if (tg < 32) {
            int e = row0 + mb * 32 + tg;
            src_s[mb * 32 + tg] = (e < N_EDGES) ? ei[e] : 0;
            dst_s[mb * 32 + tg] = (e < N_EDGES) ? ei[N_EDGES + e] : 0;
        }
        BAR_GRP(bar);

        float acc[2][8][4];

        zero_acc8(acc);
        warp_gemm(As, W1p, acc, mb, nb);        // Y1 = ea @ W1^T
        BAR_GRP(bar);

        ssp_writeback(As, b1s, acc, mb, nb, true);  // Z = tf32(ssp(Y1+b1))
        BAR_GRP(bar);

        zero_acc8(acc);
        warp_gemm(As, W2p, acc, mb, nb);        // Y2 = Z @ W2^T
        BAR_GRP(bar);

        ssp_writeback(As, b2s, acc, mb, nb, false); // W = ssp(Y2+b2)
        BAR_GRP(bar);

        // epilogue: group's 32 rows; msg = h[src]*W; red.add -> agg[dst]
        {
            const int hw = tg >> 4;     // 0..3
            const int l16 = tg & 15;
            #pragma unroll
            for (int j = 0; j < 8; ++j) {
                int m = mb * 32 + hw * 8 + j;
                int e = row0 + m;
                if (e < N_EDGES) {
                    int s = src_s[m];
                    int d = dst_s[m];
                    const float* wp = &As[m * SA + l16 * 8];
                    const float* hp = &g_h[(size_t)s * 128 + l16 * 8];
                    float* ap = &g_agg[(size_t)d * 128 + l16 * 8];
                    float4 w0 = *(const float4*)wp;
                    float4 w1 = *(const float4*)(wp + 4);
                    float4 h0 = *(const float4*)hp;
                    float4 h1 = *(const float4*)(hp + 4);
                    red_add_v4(ap, make_float4(w0.x * h0.x, w0.y * h0.y,
                                               w0.z * h0.z, w0.w * h0.w));
                    red_add_v4(ap + 4, make_float4(w1.x * h1.x, w1.y * h1.y,
                                                   w1.z * h1.z, w1.w * h1.w));
                }
            }
        }
        BAR_GRP(bar);  // As reads done before next tile's load
    }
}

// ==========================================================================
// Node h kernel (persistent, group-pipelined): h = x @ fc1^T ; zero g_agg
// ==========================================================================
#define NODE_TILES 3
#define NODE_GRID 131   // 131*3 = 393 >= 391

#define NSM_AS 0
#define NSM_W (128 * SA)
#define NSM_FLOATS (128 * SA + 16384)

__global__ void __launch_bounds__(NT, 1)
node_h_kernel(const float* __restrict__ x, const float* __restrict__ fc1_w) {
    extern __shared__ float sm[];
    float* As = &sm[NSM_AS];
    float* Wp = &sm[NSM_W];

    const int tid = threadIdx.x;
    const int mb = tid >> 6;
    const int nb = (tid >> 5) & 1;
    const int tg = tid & 63;
    const int bar = mb + 1;
    const int lid = tid & 31;
    const int gr = lid >> 2;
    const int gc = lid & 3;

    load_weights_packed(fc1_w, Wp);
    __syncthreads();

    for (int it = 0; it < NODE_TILES; ++it) {
        const int row0 = (blockIdx.x * NODE_TILES + it) * 128;
        if (row0 >= N_NODES) break;

        load_rows32(x, row0 + mb * 32, N_NODES, As, mb * 32, tg);
        BAR_GRP(bar);

        float acc[2][8][4];
        zero_acc8(acc);
        warp_gemm(As, Wp, acc, mb, nb);

        #pragma unroll
        for (int mi = 0; mi < 2; ++mi) {
            int r0 = row0 + mb * 32 + mi * 16 + gr;
            #pragma unroll
            for (int nj = 0; nj < 8; ++nj) {
                int c0 = nb * 64 + nj * 8 + 2 * gc;
                if (r0 < N_NODES)
                    *(float2*)&g_h[(size_t)r0 * 128 + c0] =
                        make_float2(acc[mi][nj][0], acc[mi][nj][1]);
                if (r0 + 8 < N_NODES)
                    *(float2*)&g_h[(size_t)(r0 + 8) * 128 + c0] =
                        make_float2(acc[mi][nj][2], acc[mi][nj][3]);
            }
        }

        // zero g_agg for this group's 32 rows
        const float4 z4 = make_float4(0.f, 0.f, 0.f, 0.f);
        #pragma unroll
        for (int i = 0; i < 16; ++i) {
            int idx = tg + i * 64;
            int r = row0 + mb * 32 + (idx >> 5);
            int q = idx & 31;
            if (r < N_NODES) *(float4*)&g_agg[(size_t)r * 128 + q * 4] = z4;
        }
        BAR_GRP(bar);  // gemm reads done before next tile's As load
    }
}

// ==========================================================================
// Final kernel (persistent, group-pipelined): out = ssp(agg @ s_w1^T) @ s_w2^T
// ==========================================================================
#define FSM_AS 0
#define FSM_W1 (128 * SA)
#define FSM_W2 (128 * SA + 16384)
#define FSM_FLOATS (128 * SA + 32768)

__global__ void __launch_bounds__(NT, 1)
final_kernel(const float* __restrict__ sw1, const float* __restrict__ sw2,
             float* __restrict__ out) {
    extern __shared__ float sm[];
    float* As = &sm[FSM_AS];
    float* W1p = &sm[FSM_W1];
    float* W2p = &sm[FSM_W2];

    const int tid = threadIdx.x;
    const int mb = tid >> 6;
    const int nb = (tid >> 5) & 1;
    const int tg = tid & 63;
    const int bar = mb + 1;
    const int lid = tid & 31;
    const int gr = lid >> 2;
    const int gc = lid & 3;

    load_weights_packed(sw1, W1p);
    load_weights_packed(sw2, W2p);
    __syncthreads();

    for (int it = 0; it < NODE_TILES; ++it) {
        const int row0 = (blockIdx.x * NODE_TILES + it) * 128;
        if (row0 >= N_NODES) break;

        load_rows32(g_agg, row0 + mb * 32, N_NODES, As, mb * 32, tg);
        BAR_GRP(bar);

        float acc[2][8][4];
        zero_acc8(acc);
        warp_gemm(As, W1p, acc, mb, nb);
        BAR_GRP(bar);

        ssp_writeback(As, (const float*)nullptr, acc, mb, nb, true);
        BAR_GRP(bar);

        zero_acc8(acc);
        warp_gemm(As, W2p, acc, mb, nb);

        #pragma unroll
        for (int mi = 0; mi < 2; ++mi) {
            int r0 = row0 + mb * 32 + mi * 16 + gr;
            #pragma unroll
            for (int nj = 0; nj < 8; ++nj) {
                int c0 = nb * 64 + nj * 8 + 2 * gc;
                if (r0 < N_NODES)
                    *(float2*)&out[(size_t)r0 * 128 + c0] =
                        make_float2(acc[mi][nj][0], acc[mi][nj][1]);
                if (r0 + 8 < N_NODES)
                    *(float2*)&out[(size_t)(r0 + 8) * 128 + c0] =
                        make_float2(acc[mi][nj][2], acc[mi][nj][3]);
            }
        }
        BAR_GRP(bar);  // gemm reads done before next tile's As load
    }
}

// ==========================================================================
extern "C" void kernel_launch(void* const* d_in, const int* in_sizes, int n_in,
                              void* d_out, int out_size) {
    const float* x = (const float*)d_in[0];
    const float* ea = (const float*)d_in[1];
    const int* ei = (const int*)d_in[2];
    const float* fc1w = (const float*)d_in[3];
    const float* fw1 = (const float*)d_in[4];
    const float* fb1 = (const float*)d_in[5];
    const float* fw2 = (const float*)d_in[6];
    const float* fb2 = (const float*)d_in[7];
    const float* sw1 = (const float*)d_in[8];
    const float* sw2 = (const float*)d_in[9];
    float* out = (float*)d_out;

    const size_t sh_edge = (size_t)ESM_FLOATS * sizeof(float);
    const size_t sh_node = (size_t)NSM_FLOATS * sizeof(float);
    const size_t sh_final = (size_t)FSM_FLOATS * sizeof(float);

    cudaFuncSetAttribute(edge_kernel, cudaFuncAttributeMaxDynamicSharedMemorySize, (int)sh_edge);
    cudaFuncSetAttribute(node_h_kernel, cudaFuncAttributeMaxDynamicSharedMemorySize, (int)sh_node);
    cudaFuncSetAttribute(final_kernel, cudaFuncAttributeMaxDynamicSharedMemorySize, (int)sh_final);

    node_h_kernel<<<NODE_GRID, NT, sh_node>>>(x, fc1w);
    edge_kernel<<<EGRID, NT, sh_edge>>>(ea, ei, fw1, fb1, fw2, fb2);
    final_kernel<<<NODE_GRID, NT, sh_final>>>(sw1, sw2, out);
}

// round 6
// speedup vs baseline: 3.1071x; 1.0982x over previous
#include <cuda_runtime.h>
#include <cstdint>
#include <math.h>

#define N_NODES 50000
#define N_EDGES 600000
#define HID 128

// Scratch
__device__ float g_h[(size_t)N_NODES * HID];    // x @ fc1_w.T
__device__ float g_agg[(size_t)N_NODES * HID];  // scatter-add accumulator

// Fast shifted softplus
__device__ __forceinline__ float sspf(float x) {
    float t = __expf(-fabsf(x));
    return fmaxf(x, 0.0f) + __logf(1.0f + t) - 0.69314718055994530942f;
}

__device__ __forceinline__ float to_tf32(float x) {
    float r;
    asm("cvt.rna.tf32.f32 %0, %1;" : "=f"(r) : "f"(x));
    return r;
}

__device__ __forceinline__ void mma16n8k8(float c[4], const uint32_t a[4],
                                          const uint32_t b[2]) {
    asm volatile(
        "mma.sync.aligned.m16n8k8.row.col.f32.tf32.tf32.f32 "
        "{%0,%1,%2,%3}, {%4,%5,%6,%7}, {%8,%9}, {%0,%1,%2,%3};"
        : "+f"(c[0]), "+f"(c[1]), "+f"(c[2]), "+f"(c[3])
        : "r"(a[0]), "r"(a[1]), "r"(a[2]), "r"(a[3]), "r"(b[0]), "r"(b[1]));
}

__device__ __forceinline__ void red_add_v4(float* addr, float4 v) {
    asm volatile("red.global.add.v4.f32 [%0], {%1, %2, %3, %4};"
                 :: "l"(addr), "f"(v.x), "f"(v.y), "f"(v.z), "f"(v.w) : "memory");
}

#define BAR_GRP(id) asm volatile("bar.sync %0, 64;" :: "r"(id) : "memory")

#define NT 512       // threads per CTA: 16 warps = 8 groups x 2 warps
#define SA 132       // padded fp32 stride of the A tile

// ==========================================================================
// Packed weight layout (proven): Wp[n*128 + wcol(k,n)] = tf32(W[n][k])
// ==========================================================================
__device__ __forceinline__ int wcol(int k, int n) {
    int pk = (k & ~15) | ((k & 3) << 2) | ((k >> 2) & 3);
    return pk ^ ((n & 1) << 4);
}

__device__ __forceinline__ void load_weights_packed(const float* __restrict__ G,
                                                    float* __restrict__ Wp) {
    for (int idx = threadIdx.x; idx < 128 * 32; idx += NT) {
        int n = idx >> 5, t = idx & 31;
        float4 v = *(const float4*)&G[n * 128 + t * 4];
        float vv[4] = {to_tf32(v.x), to_tf32(v.y), to_tf32(v.z), to_tf32(v.w)};
        #pragma unroll
        for (int i = 0; i < 4; ++i) Wp[n * 128 + wcol(t * 4 + i, n)] = vv[i];
    }
}

// Group-local load: 16 rows of a row-major [*,128] tensor into As rows
// srow0..+15 (tf32-rounded). 64 threads (tg).
__device__ __forceinline__ void load_rows16(const float* __restrict__ G, int grow0,
                                            int nrows, float* __restrict__ Sm,
                                            int srow0, int tg) {
    #pragma unroll
    for (int i = 0; i < 8; ++i) {
        int idx = tg + i * 64;   // 0..511 float4 slots
        int r = idx >> 5;
        int q = idx & 31;
        float4 v = make_float4(0.f, 0.f, 0.f, 0.f);
        if (grow0 + r < nrows) v = *(const float4*)&G[(size_t)(grow0 + r) * 128 + q * 4];
        v.x = to_tf32(v.x); v.y = to_tf32(v.y); v.z = to_tf32(v.z); v.w = to_tf32(v.w);
        *(float4*)&Sm[(srow0 + r) * SA + q * 4] = v;
    }
}

// 16x128x64 warp GEMM (rows mb*16..+15, cols nb*64..+63): acc += A * Wp^T
__device__ __forceinline__ void warp_gemm(const float* __restrict__ As,
                                          const float* __restrict__ Wp,
                                          float acc[8][4], int mb, int nb) {
    const int lid = threadIdx.x & 31;
    const int gr = lid >> 2;
    const int gc = lid & 3;
    const float* abase = As + (mb * 16 + gr) * SA + gc;
    const int nrow0 = nb * 64 + gr;
    const int nxor = (gr & 1) << 4;

    #pragma unroll
    for (int c = 0; c < 8; ++c) {
        const int k0 = c * 16;
        const float* ap0 = abase + k0;
        const float* ap1 = ap0 + 8 * SA;
        uint32_t a0[4], a1[4];
        a0[0] = __float_as_uint(ap0[0]);
        a0[1] = __float_as_uint(ap1[0]);
        a0[2] = __float_as_uint(ap0[4]);
        a0[3] = __float_as_uint(ap1[4]);
        a1[0] = __float_as_uint(ap0[8]);
        a1[1] = __float_as_uint(ap1[8]);
        a1[2] = __float_as_uint(ap0[12]);
        a1[3] = __float_as_uint(ap1[12]);
        #pragma unroll
        for (int nj = 0; nj < 8; ++nj) {
            const int n = nrow0 + 8 * nj;
            float4 bv = *(const float4*)&Wp[n * 128 + ((k0 + gc * 4) ^ nxor)];
            uint32_t b0[2] = {__float_as_uint(bv.x), __float_as_uint(bv.y)};
            uint32_t b1[2] = {__float_as_uint(bv.z), __float_as_uint(bv.w)};
            mma16n8k8(acc[nj], a0, b0);
            mma16n8k8(acc[nj], a1, b1);
        }
    }
}

__device__ __forceinline__ void zero_acc8(float acc[8][4]) {
    #pragma unroll
    for (int nj = 0; nj < 8; ++nj)
        #pragma unroll
        for (int e = 0; e < 4; ++e) acc[nj][e] = 0.0f;
}

// ssp(acc + bias) -> As rows mb*16..+15, cols nb*64..+63
__device__ __forceinline__ void ssp_writeback(float* __restrict__ Sm,
                                              const float* __restrict__ bias,
                                              float acc[8][4], int mb, int nb,
                                              bool round_tf32) {
    const int lid = threadIdx.x & 31;
    const int gr = lid >> 2;
    const int gc = lid & 3;
    int r0 = mb * 16 + gr;
    #pragma unroll
    for (int nj = 0; nj < 8; ++nj) {
        int c0 = nb * 64 + nj * 8 + 2 * gc;
        float b0 = bias ? bias[c0] : 0.0f;
        float b1v = bias ? bias[c0 + 1] : 0.0f;
        float2 lo, hi;
        lo.x = sspf(acc[nj][0] + b0);
        lo.y = sspf(acc[nj][1] + b1v);
        hi.x = sspf(acc[nj][2] + b0);
        hi.y = sspf(acc[nj][3] + b1v);
        if (round_tf32) {
            lo.x = to_tf32(lo.x); lo.y = to_tf32(lo.y);
            hi.x = to_tf32(hi.x); hi.y = to_tf32(hi.y);
        }
        *(float2*)&Sm[r0 * SA + c0] = lo;
        *(float2*)&Sm[(r0 + 8) * SA + c0] = hi;
    }
}

// ==========================================================================
// Edge kernel: 8 independent 2-warp groups, per-group named barriers
// ==========================================================================
#define TILES_PER_CTA 8
#define EGRID 586

#define ESM_IDX 0
#define ESM_B1 256
#define ESM_B2 384
#define ESM_AS 512
#define ESM_W1 (512 + 128 * SA)
#define ESM_W2 (512 + 128 * SA + 16384)
#define ESM_FLOATS (512 + 128 * SA + 32768)

__global__ void __launch_bounds__(NT, 1)
edge_kernel(const float* __restrict__ ea, const int* __restrict__ ei,
            const float* __restrict__ fw1, const float* __restrict__ fb1,
            const float* __restrict__ fw2, const float* __restrict__ fb2) {
    extern __shared__ float sm[];
    int* src_s = (int*)&sm[ESM_IDX];
    int* dst_s = src_s + 128;
    float* b1s = &sm[ESM_B1];
    float* b2s = &sm[ESM_B2];
    float* As = &sm[ESM_AS];
    float* W1p = &sm[ESM_W1];
    float* W2p = &sm[ESM_W2];

    const int tid = threadIdx.x;
    const int mb = tid >> 6;          // group 0..7: rows mb*16..+15
    const int nb = (tid >> 5) & 1;    // warp-in-group: cols nb*64..+63
    const int tg = tid & 63;          // thread-in-group
    const int bar = mb + 1;           // named barrier ids 1..8

    load_weights_packed(fw1, W1p);
    load_weights_packed(fw2, W2p);
    if (tid < 128) {
        b1s[tid] = fb1[tid];
        b2s[tid] = fb2[tid];
    }
    __syncthreads();

    for (int it = 0; it < TILES_PER_CTA; ++it) {
        const int row0 = (blockIdx.x * TILES_PER_CTA + it) * 128;
        if (row0 >= N_EDGES) break;

        // group-local loads: 16 A rows + 16 index pairs
        load_rows16(ea, row0 + mb * 16, N_EDGES, As, mb * 16, tg);
        if (tg < 16) {
            int e = row0 + mb * 16 + tg;
            src_s[mb * 16 + tg] = (e < N_EDGES) ? ei[e] : 0;
            dst_s[mb * 16 + tg] = (e < N_EDGES) ? ei[N_EDGES + e] : 0;
        }
        BAR_GRP(bar);

        float acc[8][4];

        zero_acc8(acc);
        warp_gemm(As, W1p, acc, mb, nb);            // Y1 = ea @ W1^T
        BAR_GRP(bar);

        ssp_writeback(As, b1s, acc, mb, nb, true);  // Z = tf32(ssp(Y1+b1))
        BAR_GRP(bar);

        zero_acc8(acc);
        warp_gemm(As, W2p, acc, mb, nb);            // Y2 = Z @ W2^T
        BAR_GRP(bar);

        ssp_writeback(As, b2s, acc, mb, nb, false); // W = ssp(Y2+b2)
        BAR_GRP(bar);

        // epilogue: group's 16 rows; msg = h[src]*W; red.add -> agg[dst]
        {
            const int hw = tg >> 4;     // 0..3 -> 4 rows each
            const int l16 = tg & 15;
            #pragma unroll
            for (int j = 0; j < 4; ++j) {
                int m = mb * 16 + hw * 4 + j;
                int e = row0 + m;
                if (e < N_EDGES) {
                    int s = src_s[m];
                    int d = dst_s[m];
                    const float* wp = &As[m * SA + l16 * 8];
                    const float* hp = &g_h[(size_t)s * 128 + l16 * 8];
                    float* ap = &g_agg[(size_t)d * 128 + l16 * 8];
                    float4 w0 = *(const float4*)wp;
                    float4 w1 = *(const float4*)(wp + 4);
                    float4 h0 = *(const float4*)hp;
                    float4 h1 = *(const float4*)(hp + 4);
                    red_add_v4(ap, make_float4(w0.x * h0.x, w0.y * h0.y,
                                               w0.z * h0.z, w0.w * h0.w));
                    red_add_v4(ap + 4, make_float4(w1.x * h1.x, w1.y * h1.y,
                                                   w1.z * h1.z, w1.w * h1.w));
                }
            }
        }
        BAR_GRP(bar);  // As reads done before next tile's load
    }
}

// ==========================================================================
// Node h kernel (persistent, grouped): h = x @ fc1^T ; zero g_agg
// ==========================================================================
#define NODE_TILES 2
#define NODE_GRID 196   // 196*2 = 392 >= 391

#define NSM_AS 0
#define NSM_W (128 * SA)
#define NSM_FLOATS (128 * SA + 16384)

__global__ void __launch_bounds__(NT, 1)
node_h_kernel(const float* __restrict__ x, const float* __restrict__ fc1_w) {
    extern __shared__ float sm[];
    float* As = &sm[NSM_AS];
    float* Wp = &sm[NSM_W];

    const int tid = threadIdx.x;
    const int mb = tid >> 6;
    const int nb = (tid >> 5) & 1;
    const int tg = tid & 63;
    const int bar = mb + 1;
    const int lid = tid & 31;
    const int gr = lid >> 2;
    const int gc = lid & 3;

    load_weights_packed(fc1_w, Wp);
    __syncthreads();

    for (int it = 0; it < NODE_TILES; ++it) {
        const int row0 = (blockIdx.x * NODE_TILES + it) * 128;
        if (row0 >= N_NODES) break;

        load_rows16(x, row0 + mb * 16, N_NODES, As, mb * 16, tg);
        BAR_GRP(bar);

        float acc[8][4];
        zero_acc8(acc);
        warp_gemm(As, Wp, acc, mb, nb);

        int r0 = row0 + mb * 16 + gr;
        #pragma unroll
        for (int nj = 0; nj < 8; ++nj) {
            int c0 = nb * 64 + nj * 8 + 2 * gc;
            if (r0 < N_NODES)
                *(float2*)&g_h[(size_t)r0 * 128 + c0] =
                    make_float2(acc[nj][0], acc[nj][1]);
            if (r0 + 8 < N_NODES)
                *(float2*)&g_h[(size_t)(r0 + 8) * 128 + c0] =
                    make_float2(acc[nj][2], acc[nj][3]);
        }

        // zero g_agg for this group's 16 rows
        const float4 z4 = make_float4(0.f, 0.f, 0.f, 0.f);
        #pragma unroll
        for (int i = 0; i < 8; ++i) {
            int idx = tg + i * 64;
            int r = row0 + mb * 16 + (idx >> 5);
            int q = idx & 31;
            if (r < N_NODES) *(float4*)&g_agg[(size_t)r * 128 + q * 4] = z4;
        }
        BAR_GRP(bar);  // gemm reads done before next tile's As load
    }
}

// ==========================================================================
// Final kernel (persistent, grouped): out = ssp(agg @ s_w1^T) @ s_w2^T
// ==========================================================================
#define FSM_AS 0
#define FSM_W1 (128 * SA)
#define FSM_W2 (128 * SA + 16384)
#define FSM_FLOATS (128 * SA + 32768)

__global__ void __launch_bounds__(NT, 1)
final_kernel(const float* __restrict__ sw1, const float* __restrict__ sw2,
             float* __restrict__ out) {
    extern __shared__ float sm[];
    float* As = &sm[FSM_AS];
    float* W1p = &sm[FSM_W1];
    float* W2p = &sm[FSM_W2];

    const int tid = threadIdx.x;
    const int mb = tid >> 6;
    const int nb = (tid >> 5) & 1;
    const int tg = tid & 63;
    const int bar = mb + 1;
    const int lid = tid & 31;
    const int gr = lid >> 2;
    const int gc = lid & 3;

    load_weights_packed(sw1, W1p);
    load_weights_packed(sw2, W2p);
    __syncthreads();

    for (int it = 0; it < NODE_TILES; ++it) {
        const int row0 = (blockIdx.x * NODE_TILES + it) * 128;
        if (row0 >= N_NODES) break;

        load_rows16(g_agg, row0 + mb * 16, N_NODES, As, mb * 16, tg);
        BAR_GRP(bar);

        float acc[8][4];
        zero_acc8(acc);
        warp_gemm(As, W1p, acc, mb, nb);
        BAR_GRP(bar);

        ssp_writeback(As, (const float*)nullptr, acc, mb, nb, true);
        BAR_GRP(bar);

        zero_acc8(acc);
        warp_gemm(As, W2p, acc, mb, nb);

        int r0 = row0 + mb * 16 + gr;
        #pragma unroll
        for (int nj = 0; nj < 8; ++nj) {
            int c0 = nb * 64 + nj * 8 + 2 * gc;
            if (r0 < N_NODES)
                *(float2*)&out[(size_t)r0 * 128 + c0] =
                    make_float2(acc[nj][0], acc[nj][1]);
            if (r0 + 8 < N_NODES)
                *(float2*)&out[(size_t)(r0 + 8) * 128 + c0] =
                    make_float2(acc[nj][2], acc[nj][3]);
        }
        BAR_GRP(bar);  // gemm reads done before next tile's As load
    }
}

// ==========================================================================
extern "C" void kernel_launch(void* const* d_in, const int* in_sizes, int n_in,
                              void* d_out, int out_size) {
    const float* x = (const float*)d_in[0];
    const float* ea = (const float*)d_in[1];
    const int* ei = (const int*)d_in[2];
    const float* fc1w = (const float*)d_in[3];
    const float* fw1 = (const float*)d_in[4];
    const float* fb1 = (const float*)d_in[5];
    const float* fw2 = (const float*)d_in[6];
    const float* fb2 = (const float*)d_in[7];
    const float* sw1 = (const float*)d_in[8];
    const float* sw2 = (const float*)d_in[9];
    float* out = (float*)d_out;

    const size_t sh_edge = (size_t)ESM_FLOATS * sizeof(float);
    const size_t sh_node = (size_t)NSM_FLOATS * sizeof(float);
    const size_t sh_final = (size_t)FSM_FLOATS * sizeof(float);

    cudaFuncSetAttribute(edge_kernel, cudaFuncAttributeMaxDynamicSharedMemorySize, (int)sh_edge);
    cudaFuncSetAttribute(node_h_kernel, cudaFuncAttributeMaxDynamicSharedMemorySize, (int)sh_node);
    cudaFuncSetAttribute(final_kernel, cudaFuncAttributeMaxDynamicSharedMemorySize, (int)sh_final);

    node_h_kernel<<<NODE_GRID, NT, sh_node>>>(x, fc1w);
    edge_kernel<<<EGRID, NT, sh_edge>>>(ea, ei, fw1, fb1, fw2, fb2);
    final_kernel<<<NODE_GRID, NT, sh_final>>>(sw1, sw2, out);
}